// round 6
// baseline (speedup 1.0000x reference)
#include <cuda_runtime.h>

#define NB   8
#define NH   32
#define NW   32
#define NC   32
#define HO   30
#define WO   30
#define NF   64
#define NK   288   // 3*3*32

// Exact prune threshold: max over filters of (max_k w - min_k w).
__device__ float g_T;

// 1024 threads: 16 k-chunks x 64 filters, 18 independent L2 loads each.
__global__ __launch_bounds__(1024) void trop_T_kernel(const float* __restrict__ w) {
    __shared__ float smax[16][64];
    __shared__ float smin[16][64];
    int t = threadIdx.x;
    int f = t & 63;
    int chunk = t >> 6;
    int k0 = chunk * 18;
    float wmax = -1e30f, wmin = 1e30f;
#pragma unroll
    for (int q = 0; q < 18; q++) {
        float v = w[(k0 + q) * NF + f];
        wmax = fmaxf(wmax, v);
        wmin = fminf(wmin, v);
    }
    smax[chunk][f] = wmax;
    smin[chunk][f] = wmin;
    __syncthreads();
    if (t < 32) {
        float a0 = -1e30f, b0 = 1e30f, a1 = -1e30f, b1 = 1e30f;
#pragma unroll
        for (int q = 0; q < 16; q++) {
            a0 = fmaxf(a0, smax[q][t]);      b0 = fminf(b0, smin[q][t]);
            a1 = fmaxf(a1, smax[q][t + 32]); b1 = fminf(b1, smin[q][t + 32]);
        }
        float r = fmaxf(a0 - b0, a1 - b1);
#pragma unroll
        for (int o = 16; o; o >>= 1)
            r = fmaxf(r, __shfl_xor_sync(0xffffffffu, r, o));
        if (t == 0) g_T = r;
    }
}

// Block = (b, ho, wgroup of 10 wo). 320 threads = 10 warps, warp = position,
// lane = channel.
__global__ __launch_bounds__(320) void trop_main_kernel(
    const float* __restrict__ x, const float* __restrict__ w,
    const float* __restrict__ bias, float* __restrict__ out) {

    int bx = blockIdx.x;
    int wg = bx % 3;
    int ho = (bx / 3) % HO;
    int b  = bx / (3 * HO);

    __shared__ float s[3][12 * NC];           // 4608 B patch
    __shared__ short candmax[10][NK];         // 5760 B
    __shared__ short candmin[10][NK];         // 5760 B
    __shared__ int   cnt[10][8];              // padded: warp's counters on own banks

    int t = threadIdx.x;

    // Phase 1: contiguous float4 patch load (3 rows x 12 cols x 32 ch).
    if (t < 288) {
        int row = t / 96;
        int q   = t - row * 96;
        const float4* src = (const float4*)(x + ((b * NH + ho + row) * NW + wg * 10) * NC);
        ((float4*)s[row])[q] = src[q];
    }
    __syncthreads();

    int wp   = t >> 5;
    int lane = t & 31;
    int wo   = wg * 10 + wp;

    if (lane < 2) cnt[wp][lane] = 0;

    // Phase 2: 9 window values in registers; interleaved SHFL butterfly for
    // patch max/min (two independent chains overlap their latency).
    float v[9];
    float mx = -1e30f, mn = 1e30f;
#pragma unroll
    for (int i = 0; i < 3; i++)
#pragma unroll
        for (int j = 0; j < 3; j++) {
            float val = s[i][(wp + j) * NC + lane];
            v[i * 3 + j] = val;
            mx = fmaxf(mx, val);
            mn = fminf(mn, val);
        }
#pragma unroll
    for (int o = 16; o; o >>= 1) {
        float a = __shfl_xor_sync(0xffffffffu, mx, o);
        float bq = __shfl_xor_sync(0xffffffffu, mn, o);
        mx = fmaxf(mx, a);
        mn = fminf(mn, bq);
    }

    // Phase 3: exact prune + per-warp candidate compaction (k only). Order of
    // the compacted list is nondeterministic, but max/min over a set is
    // order-independent -> deterministic output.
    float T = g_T;
    float th_hi = mx - T;
    float th_lo = mn + T;

#pragma unroll
    for (int cell = 0; cell < 9; cell++) {
        float val = v[cell];
        if (val >= th_hi) candmax[wp][atomicAdd(&cnt[wp][0], 1)] = (short)(cell * 32 + lane);
        if (val <= th_lo) candmin[wp][atomicAdd(&cnt[wp][1], 1)] = (short)(cell * 32 + lane);
    }
    __syncwarp();
    int nmax = cnt[wp][0];
    int nmin = cnt[wp][1];

    // Phase 4: uniform candidate loops; each lane covers filters lane, lane+32.
    float amax0 = -1e30f, amax1 = -1e30f;
#pragma unroll 1
    for (int a = 0; a < nmax; a++) {
        int k = candmax[wp][a];              // LDS broadcast
        int cell = k >> 5, c = k & 31;
        int i = (cell * 11) >> 5;            // cell/3 for cell in 0..8
        int j = cell - i * 3;
        float pv = s[i][(wp + j) * NC + c];  // LDS broadcast
        const float* wr = w + k * NF;
        amax0 = fmaxf(amax0, pv + wr[lane]);
        amax1 = fmaxf(amax1, pv + wr[lane + 32]);
    }
    float amin0 = 1e30f, amin1 = 1e30f;
#pragma unroll 1
    for (int a = 0; a < nmin; a++) {
        int k = candmin[wp][a];
        int cell = k >> 5, c = k & 31;
        int i = (cell * 11) >> 5;
        int j = cell - i * 3;
        float pv = s[i][(wp + j) * NC + c];
        const float* wr = w + k * NF;
        amin0 = fminf(amin0, pv + wr[lane]);
        amin1 = fminf(amin1, pv + wr[lane + 32]);
    }

    // Phase 5: combine + bias, coalesced store.
    int pos = (b * HO + ho) * WO + wo;
    out[pos * NF + lane]      = amax0 - amin0 + bias[lane];
    out[pos * NF + lane + 32] = amax1 - amin1 + bias[lane + 32];
}

extern "C" void kernel_launch(void* const* d_in, const int* in_sizes, int n_in,
                              void* d_out, int out_size) {
    (void)in_sizes; (void)n_in; (void)out_size;
    const float* x    = (const float*)d_in[0];
    const float* w    = (const float*)d_in[1];
    const float* bias = (const float*)d_in[2];
    float* out = (float*)d_out;

    trop_T_kernel<<<1, 1024>>>(w);
    trop_main_kernel<<<NB * HO * 3, 320>>>(x, w, bias, out);
}